// round 1
// baseline (speedup 1.0000x reference)
#include <cuda_runtime.h>
#include <math.h>

#define N0 8192
#define N1 4096
#define N2 8192
// W0: [N0, N1] row-major, W1: [N1, N2] row-major

// Persistent state (device globals — no allocation allowed)
__device__ float g_x1[N1];
__device__ float g_x2[N2];
__device__ float g_e0[N0];
__device__ float g_e1[N1];
__device__ float g_g1[N1];
__device__ float g_g2[N2];

// ---------------------------------------------------------------------------
// Init: zero state, grads, and the output accumulator.
// ---------------------------------------------------------------------------
__global__ void k_init(float* __restrict__ out) {
    int i = blockIdx.x * blockDim.x + threadIdx.x;
    if (i < N1) { g_x1[i] = 0.f; g_g1[i] = 0.f; g_e1[i] = 0.f; }
    if (i < N2) { g_x2[i] = 0.f; g_g2[i] = 0.f; }
    if (i < N0) { g_e0[i] = 0.f; }
    if (i == 0) out[0] = 0.f;
}

// ---------------------------------------------------------------------------
// mu pass: warp-per-row GEMV.
//   warps [0, N0):      e0[j] = x0[j] - tanh(W0[j,:] . x1)
//   warps [N0, N0+N1):  e1[j] = x1[j] - tanh(W1[j,:] . x2)
// ---------------------------------------------------------------------------
__global__ void k_mu(const float* __restrict__ x0,
                     const float* __restrict__ W0,
                     const float* __restrict__ W1) {
    int warp = (blockIdx.x * blockDim.x + threadIdx.x) >> 5;
    int lane = threadIdx.x & 31;

    if (warp < N0) {
        const float4* row = (const float4*)(W0 + (size_t)warp * N1);
        const float4* xv  = (const float4*)g_x1;
        float acc = 0.f;
        #pragma unroll 4
        for (int i = lane; i < N1 / 4; i += 32) {
            float4 w = row[i];
            float4 x = xv[i];
            acc += w.x * x.x + w.y * x.y + w.z * x.z + w.w * x.w;
        }
        #pragma unroll
        for (int o = 16; o; o >>= 1) acc += __shfl_xor_sync(0xFFFFFFFFu, acc, o);
        if (lane == 0) g_e0[warp] = x0[warp] - tanhf(acc);
    } else {
        int r = warp - N0;
        const float4* row = (const float4*)(W1 + (size_t)r * N2);
        const float4* xv  = (const float4*)g_x2;
        float acc = 0.f;
        #pragma unroll 4
        for (int i = lane; i < N2 / 4; i += 32) {
            float4 w = row[i];
            float4 x = xv[i];
            acc += w.x * x.x + w.y * x.y + w.z * x.z + w.w * x.w;
        }
        #pragma unroll
        for (int o = 16; o; o >>= 1) acc += __shfl_xor_sync(0xFFFFFFFFu, acc, o);
        if (lane == 0) g_e1[r] = g_x1[r] - tanhf(acc);
    }
}

// ---------------------------------------------------------------------------
// grad pass: column-tiled GEMV-T with row-splitting + float atomics.
//   g1 = W0^T @ e0   (4096)   blocks [0,128): 4 col-tiles x 32 row-segs
//   g2 = W1^T @ e1   (8192)   blocks [128,256): 8 col-tiles x 16 row-segs
// Each block: 256 threads, thread owns 4 consecutive columns (float4),
// accumulates over 256 rows, then 4 atomicAdds.
// ---------------------------------------------------------------------------
__global__ void k_grad(const float* __restrict__ W0,
                       const float* __restrict__ W1) {
    int b = blockIdx.x;
    const float* W;
    const float* e;
    float* g;
    int cols, colBase, row0;
    if (b < 128) {
        int cb = b & 3;           // 4 column blocks of 1024 cols
        int rs = b >> 2;          // 32 row segments of 256 rows
        W = W0; e = g_e0; g = g_g1;
        cols = N1; colBase = cb * 1024; row0 = rs * 256;
    } else {
        b -= 128;
        int cb = b & 7;           // 8 column blocks of 1024 cols
        int rs = b >> 3;          // 16 row segments of 256 rows
        W = W1; e = g_e1; g = g_g2;
        cols = N2; colBase = cb * 1024; row0 = rs * 256;
    }
    int c = colBase + threadIdx.x * 4;
    const float* Wp = W + (size_t)row0 * cols + c;
    const float* ep = e + row0;

    float4 acc = make_float4(0.f, 0.f, 0.f, 0.f);
    #pragma unroll 4
    for (int j = 0; j < 256; j++) {
        float ev = __ldg(ep + j);
        float4 w = *(const float4*)(Wp + (size_t)j * cols);
        acc.x += ev * w.x;
        acc.y += ev * w.y;
        acc.z += ev * w.z;
        acc.w += ev * w.w;
    }
    atomicAdd(&g[c + 0], acc.x);
    atomicAdd(&g[c + 1], acc.y);
    atomicAdd(&g[c + 2], acc.z);
    atomicAdd(&g[c + 3], acc.w);
}

// ---------------------------------------------------------------------------
// update pass: apply clipped gradient step + tanh, and zero grads for reuse.
// ---------------------------------------------------------------------------
__global__ void k_update() {
    int i = blockIdx.x * blockDim.x + threadIdx.x;
    if (i < N1) {
        float gr = fminf(fmaxf(-g_e1[i] + g_g1[i], -1.f), 1.f);
        g_x1[i] = tanhf(g_x1[i] + 0.01f * gr);
        g_g1[i] = 0.f;
    } else {
        int c = i - N1;
        float x2 = g_x2[c];
        float gr = fminf(fmaxf(-x2 + g_g2[c], -1.f), 1.f);
        g_x2[c] = tanhf(x2 + 0.01f * gr);
        g_g2[c] = 0.f;
    }
}

// ---------------------------------------------------------------------------
// Final step: only the error of the last step is needed.
//   err = ||x0 - tanh(W0@x1)||^2 + ||x1 - tanh(W1@x2)||^2 + ||x2||^2
// Same warp-per-row layout as k_mu; W0 rows also fold in x2[j]^2 (N2 == N0).
// ---------------------------------------------------------------------------
__global__ void k_final(const float* __restrict__ x0,
                        const float* __restrict__ W0,
                        const float* __restrict__ W1,
                        float* __restrict__ out) {
    __shared__ float s_part[8];
    int warpInBlock = threadIdx.x >> 5;
    int warp = (blockIdx.x * blockDim.x + threadIdx.x) >> 5;
    int lane = threadIdx.x & 31;

    float local = 0.f;
    if (warp < N0) {
        const float4* row = (const float4*)(W0 + (size_t)warp * N1);
        const float4* xv  = (const float4*)g_x1;
        float acc = 0.f;
        #pragma unroll 4
        for (int i = lane; i < N1 / 4; i += 32) {
            float4 w = row[i];
            float4 x = xv[i];
            acc += w.x * x.x + w.y * x.y + w.z * x.z + w.w * x.w;
        }
        #pragma unroll
        for (int o = 16; o; o >>= 1) acc += __shfl_xor_sync(0xFFFFFFFFu, acc, o);
        if (lane == 0) {
            float e = x0[warp] - tanhf(acc);
            float x2v = g_x2[warp];      // e2 = x2, N2 == N0
            local = e * e + x2v * x2v;
        }
    } else {
        int r = warp - N0;
        const float4* row = (const float4*)(W1 + (size_t)r * N2);
        const float4* xv  = (const float4*)g_x2;
        float acc = 0.f;
        #pragma unroll 4
        for (int i = lane; i < N2 / 4; i += 32) {
            float4 w = row[i];
            float4 x = xv[i];
            acc += w.x * x.x + w.y * x.y + w.z * x.z + w.w * x.w;
        }
        #pragma unroll
        for (int o = 16; o; o >>= 1) acc += __shfl_xor_sync(0xFFFFFFFFu, acc, o);
        if (lane == 0) {
            float e = g_x1[r] - tanhf(acc);
            local = e * e;
        }
    }

    if (lane == 0) s_part[warpInBlock] = local;
    __syncthreads();
    if (threadIdx.x == 0) {
        float s = 0.f;
        #pragma unroll
        for (int w = 0; w < 8; w++) s += s_part[w];
        atomicAdd(out, s);
    }
}

// ---------------------------------------------------------------------------
// Launch: 1 init + 9 x (mu, grad, update) + final. All on default stream,
// graph-capturable, allocation-free. steps is fixed at 10 by setup_inputs.
// ---------------------------------------------------------------------------
extern "C" void kernel_launch(void* const* d_in, const int* in_sizes, int n_in,
                              void* d_out, int out_size) {
    const float* x0 = (const float*)d_in[0];
    const float* W0 = (const float*)d_in[1];
    const float* W1 = (const float*)d_in[2];
    float* out = (float*)d_out;

    const int STEPS = 10;

    k_init<<<32, 256>>>(out);
    for (int s = 0; s < STEPS - 1; s++) {
        k_mu<<<(N0 + N1) / 8, 256>>>(x0, W0, W1);
        k_grad<<<256, 256>>>(W0, W1);
        k_update<<<(N1 + N2) / 256, 256>>>();
    }
    k_final<<<(N0 + N1) / 8, 256>>>(x0, W0, W1, out);
}

// round 2
// speedup vs baseline: 1.1200x; 1.1200x over previous
#include <cuda_runtime.h>
#include <math.h>

#define N0 8192
#define N1 4096
#define N2 8192
// W0: [N0, N1] row-major, W1: [N1, N2] row-major

// Persistent state (device globals — allocation-free scratch)
__device__ float g_x1[N1];
__device__ float g_x2[N2];
__device__ float g_e1[N1];
__device__ float g_g1[N1];
__device__ float g_g2[N2];

// ---------------------------------------------------------------------------
__global__ void k_init(float* __restrict__ out) {
    int i = blockIdx.x * blockDim.x + threadIdx.x;
    if (i < N1) { g_x1[i] = 0.f; g_g1[i] = 0.f; g_e1[i] = 0.f; }
    if (i < N2) { g_x2[i] = 0.f; g_g2[i] = 0.f; }
    if (i == 0) out[0] = 0.f;
}

// ---------------------------------------------------------------------------
// Fused step: one DRAM pass over each weight matrix computes BOTH
//   e[j] = x_prev[j] - tanh(W[j,:] . x)        (row dot)
//   g   += e[j] * W[j,:]                        (transposed accumulation)
// Phase 1: warp-per-row dots for a 16-row tile (DRAM read).
// Phase 2: re-read tile from L2, thread-owned column slices, register accs.
// Blocks [0,128): W0 (64 rows each).  Blocks [128,256): W1 (32 rows each).
// ---------------------------------------------------------------------------
__global__ void __launch_bounds__(256) k_step(const float* __restrict__ x0,
                                              const float* __restrict__ W0,
                                              const float* __restrict__ W1) {
    __shared__ float se[16];
    const int tid  = threadIdx.x;
    const int warp = tid >> 5;
    const int lane = tid & 31;

    if (blockIdx.x < 128) {
        // ---------------- W0 half: rows of [8192 x 4096] ----------------
        const int rowBase = blockIdx.x * 64;
        float4 acc[4] = {make_float4(0,0,0,0), make_float4(0,0,0,0),
                         make_float4(0,0,0,0), make_float4(0,0,0,0)};
        const float4* xv = (const float4*)g_x1;

        #pragma unroll 1
        for (int t = 0; t < 4; t++) {
            const int rb = rowBase + t * 16;
            // Phase 1: dots (each warp: rows warp, warp+8)
            #pragma unroll
            for (int r = warp; r < 16; r += 8) {
                const float4* row = (const float4*)(W0 + (size_t)(rb + r) * N1);
                float a0 = 0.f, a1 = 0.f;
                #pragma unroll 4
                for (int i = lane; i < N1 / 4; i += 64) {
                    float4 w = row[i],      x = xv[i];
                    a0 += w.x*x.x + w.y*x.y + w.z*x.z + w.w*x.w;
                    float4 w2 = row[i + 32], x2 = xv[i + 32];
                    a1 += w2.x*x2.x + w2.y*x2.y + w2.z*x2.z + w2.w*x2.w;
                }
                float a = a0 + a1;
                #pragma unroll
                for (int o = 16; o; o >>= 1) a += __shfl_xor_sync(0xFFFFFFFFu, a, o);
                if (lane == 0) se[r] = x0[rb + r] - tanhf(a);
            }
            __syncthreads();
            // Phase 2: rank-16 update from L2-hot tile
            #pragma unroll 4
            for (int j = 0; j < 16; j++) {
                const float ev = se[j];
                const float4* row = (const float4*)(W0 + (size_t)(rb + j) * N1);
                #pragma unroll
                for (int k = 0; k < 4; k++) {
                    float4 w = __ldg(&row[tid + k * 256]);
                    acc[k].x += ev * w.x;
                    acc[k].y += ev * w.y;
                    acc[k].z += ev * w.z;
                    acc[k].w += ev * w.w;
                }
            }
            __syncthreads();
        }
        #pragma unroll
        for (int k = 0; k < 4; k++) {
            const int c = 4 * (tid + k * 256);
            atomicAdd(&g_g1[c + 0], acc[k].x);
            atomicAdd(&g_g1[c + 1], acc[k].y);
            atomicAdd(&g_g1[c + 2], acc[k].z);
            atomicAdd(&g_g1[c + 3], acc[k].w);
        }
    } else {
        // ---------------- W1 half: rows of [4096 x 8192] ----------------
        const int rowBase = (blockIdx.x - 128) * 32;
        float4 acc[8] = {make_float4(0,0,0,0), make_float4(0,0,0,0),
                         make_float4(0,0,0,0), make_float4(0,0,0,0),
                         make_float4(0,0,0,0), make_float4(0,0,0,0),
                         make_float4(0,0,0,0), make_float4(0,0,0,0)};
        const float4* xv = (const float4*)g_x2;

        #pragma unroll 1
        for (int t = 0; t < 2; t++) {
            const int rb = rowBase + t * 16;
            // Phase 1: dots + write e1 to global
            #pragma unroll
            for (int r = warp; r < 16; r += 8) {
                const float4* row = (const float4*)(W1 + (size_t)(rb + r) * N2);
                float a0 = 0.f, a1 = 0.f;
                #pragma unroll 4
                for (int i = lane; i < N2 / 4; i += 64) {
                    float4 w = row[i],      x = xv[i];
                    a0 += w.x*x.x + w.y*x.y + w.z*x.z + w.w*x.w;
                    float4 w2 = row[i + 32], x2 = xv[i + 32];
                    a1 += w2.x*x2.x + w2.y*x2.y + w2.z*x2.z + w2.w*x2.w;
                }
                float a = a0 + a1;
                #pragma unroll
                for (int o = 16; o; o >>= 1) a += __shfl_xor_sync(0xFFFFFFFFu, a, o);
                if (lane == 0) {
                    float e = g_x1[rb + r] - tanhf(a);
                    se[r] = e;
                    g_e1[rb + r] = e;
                }
            }
            __syncthreads();
            // Phase 2: rank-16 update from L2-hot tile
            #pragma unroll 2
            for (int j = 0; j < 16; j++) {
                const float ev = se[j];
                const float4* row = (const float4*)(W1 + (size_t)(rb + j) * N2);
                #pragma unroll
                for (int k = 0; k < 8; k++) {
                    float4 w = __ldg(&row[tid + k * 256]);
                    acc[k].x += ev * w.x;
                    acc[k].y += ev * w.y;
                    acc[k].z += ev * w.z;
                    acc[k].w += ev * w.w;
                }
            }
            __syncthreads();
        }
        #pragma unroll
        for (int k = 0; k < 8; k++) {
            const int c = 4 * (tid + k * 256);
            atomicAdd(&g_g2[c + 0], acc[k].x);
            atomicAdd(&g_g2[c + 1], acc[k].y);
            atomicAdd(&g_g2[c + 2], acc[k].z);
            atomicAdd(&g_g2[c + 3], acc[k].w);
        }
    }
}

// ---------------------------------------------------------------------------
// State update: x1 <- tanh(x1 + 0.01*clip(-e1 + g1)), x2 <- tanh(x2 + 0.01*clip(-x2 + g2))
// Also zeroes g1/g2 for the next step.
// ---------------------------------------------------------------------------
__global__ void k_update() {
    int i = blockIdx.x * blockDim.x + threadIdx.x;
    if (i < N1) {
        float gr = fminf(fmaxf(-g_e1[i] + g_g1[i], -1.f), 1.f);
        g_x1[i] = tanhf(g_x1[i] + 0.01f * gr);
        g_g1[i] = 0.f;
    } else {
        int c = i - N1;
        float x2 = g_x2[c];
        float gr = fminf(fmaxf(-x2 + g_g2[c], -1.f), 1.f);
        g_x2[c] = tanhf(x2 + 0.01f * gr);
        g_g2[c] = 0.f;
    }
}

// ---------------------------------------------------------------------------
// Final step: err = ||x0 - tanh(W0@x1)||^2 + ||x1 - tanh(W1@x2)||^2 + ||x2||^2
// Warp-per-row; W0 rows fold in x2[j]^2 (N2 == N0).
// ---------------------------------------------------------------------------
__global__ void k_final(const float* __restrict__ x0,
                        const float* __restrict__ W0,
                        const float* __restrict__ W1,
                        float* __restrict__ out) {
    __shared__ float s_part[8];
    int warpInBlock = threadIdx.x >> 5;
    int warp = (blockIdx.x * blockDim.x + threadIdx.x) >> 5;
    int lane = threadIdx.x & 31;

    float local = 0.f;
    if (warp < N0) {
        const float4* row = (const float4*)(W0 + (size_t)warp * N1);
        const float4* xv  = (const float4*)g_x1;
        float acc = 0.f;
        #pragma unroll 4
        for (int i = lane; i < N1 / 4; i += 32) {
            float4 w = row[i];
            float4 x = xv[i];
            acc += w.x*x.x + w.y*x.y + w.z*x.z + w.w*x.w;
        }
        #pragma unroll
        for (int o = 16; o; o >>= 1) acc += __shfl_xor_sync(0xFFFFFFFFu, acc, o);
        if (lane == 0) {
            float e = x0[warp] - tanhf(acc);
            float x2v = g_x2[warp];
            local = e * e + x2v * x2v;
        }
    } else {
        int r = warp - N0;
        const float4* row = (const float4*)(W1 + (size_t)r * N2);
        const float4* xv  = (const float4*)g_x2;
        float acc = 0.f;
        #pragma unroll 4
        for (int i = lane; i < N2 / 4; i += 32) {
            float4 w = row[i];
            float4 x = xv[i];
            acc += w.x*x.x + w.y*x.y + w.z*x.z + w.w*x.w;
        }
        #pragma unroll
        for (int o = 16; o; o >>= 1) acc += __shfl_xor_sync(0xFFFFFFFFu, acc, o);
        if (lane == 0) {
            float e = g_x1[r] - tanhf(acc);
            local = e * e;
        }
    }

    if (lane == 0) s_part[warpInBlock] = local;
    __syncthreads();
    if (threadIdx.x == 0) {
        float s = 0.f;
        #pragma unroll
        for (int w = 0; w < 8; w++) s += s_part[w];
        atomicAdd(out, s);
    }
}

// ---------------------------------------------------------------------------
extern "C" void kernel_launch(void* const* d_in, const int* in_sizes, int n_in,
                              void* d_out, int out_size) {
    const float* x0 = (const float*)d_in[0];
    const float* W0 = (const float*)d_in[1];
    const float* W1 = (const float*)d_in[2];
    float* out = (float*)d_out;

    const int STEPS = 10;

    k_init<<<32, 256>>>(out);
    for (int s = 0; s < STEPS - 1; s++) {
        k_step<<<256, 256>>>(x0, W0, W1);
        k_update<<<(N1 + N2) / 256, 256>>>();
    }
    k_final<<<(N0 + N1) / 8, 256>>>(x0, W0, W1, out);
}

// round 3
// speedup vs baseline: 2.0889x; 1.8650x over previous
#include <cuda_runtime.h>
#include <math.h>

#define N0 8192
#define N1 4096
#define N2 8192
// W0: [N0, N1] row-major, W1: [N1, N2] row-major

// Persistent state (device globals — allocation-free scratch)
__device__ float g_x1[N1];
__device__ float g_x2[N2];
__device__ float g_e1[N1];
__device__ float g_g1[N1];
__device__ float g_g2[N2];

__device__ __forceinline__ float dot4(float4 a, float4 b) {
    return a.x * b.x + a.y * b.y + a.z * b.z + a.w * b.w;
}

// ---------------------------------------------------------------------------
__global__ void k_init(float* __restrict__ out) {
    int i = blockIdx.x * blockDim.x + threadIdx.x;
    if (i < N1) { g_x1[i] = 0.f; g_g1[i] = 0.f; g_e1[i] = 0.f; }
    if (i < N2) { g_x2[i] = 0.f; g_g2[i] = 0.f; }
    if (i == 0) out[0] = 0.f;
}

// ---------------------------------------------------------------------------
// Fused step, register-tiled: each W element is read from DRAM exactly ONCE.
// Thread owns a fixed set of float4 columns. Per row-tile:
//   phase 1: load tile into registers (batched LDG.128 -> deep MLP),
//            per-thread partial dots, warp shuffle-reduce, smem combine -> e[r]
//   phase 2: rank-k update from the SAME registers into column accumulators.
// Blocks [0,128): W0, 64 rows each (8 tiles x 8 rows).
// Blocks [128,256): W1, 32 rows each (8 tiles x 4 rows).
// Column accumulators flushed once per block via atomicAdd.
// ---------------------------------------------------------------------------
__global__ void __launch_bounds__(512) k_step(const float* __restrict__ x0,
                                              const float* __restrict__ W0,
                                              const float* __restrict__ W1) {
    __shared__ float sp[8][16];
    __shared__ float se[8];
    const int tid  = threadIdx.x;
    const int warp = tid >> 5;
    const int lane = tid & 31;

    if (blockIdx.x < 128) {
        // ---------------- W0 half: [8192 x 4096] ----------------
        const int rowBase = blockIdx.x * 64;
        const float4* xv = (const float4*)g_x1;          // 1024 float4
        const float4 xA = xv[tid];
        const float4 xB = xv[tid + 512];
        float4 accA = make_float4(0,0,0,0);
        float4 accB = make_float4(0,0,0,0);

        #pragma unroll 1
        for (int t = 0; t < 8; t++) {
            const int rb = rowBase + t * 8;
            const float4* base = (const float4*)W0 + (size_t)rb * 1024 + tid;

            float4 wA[8], wB[8];
            #pragma unroll
            for (int r = 0; r < 8; r++) {
                wA[r] = base[(size_t)r * 1024];
                wB[r] = base[(size_t)r * 1024 + 512];
            }
            // partial dots + warp reduce
            #pragma unroll
            for (int r = 0; r < 8; r++) {
                float p = dot4(wA[r], xA) + dot4(wB[r], xB);
                #pragma unroll
                for (int o = 16; o; o >>= 1) p += __shfl_xor_sync(0xFFFFFFFFu, p, o);
                if (lane == 0) sp[r][warp] = p;
            }
            __syncthreads();
            if (tid < 8) {
                float s = 0.f;
                #pragma unroll
                for (int w = 0; w < 16; w++) s += sp[tid][w];
                se[tid] = x0[rb + tid] - tanhf(s);
            }
            __syncthreads();
            // rank-8 update from registers
            #pragma unroll
            for (int r = 0; r < 8; r++) {
                const float e = se[r];
                accA.x += e * wA[r].x;  accA.y += e * wA[r].y;
                accA.z += e * wA[r].z;  accA.w += e * wA[r].w;
                accB.x += e * wB[r].x;  accB.y += e * wB[r].y;
                accB.z += e * wB[r].z;  accB.w += e * wB[r].w;
            }
        }
        const int cA = 4 * tid;
        const int cB = 4 * (tid + 512);
        atomicAdd(&g_g1[cA + 0], accA.x);
        atomicAdd(&g_g1[cA + 1], accA.y);
        atomicAdd(&g_g1[cA + 2], accA.z);
        atomicAdd(&g_g1[cA + 3], accA.w);
        atomicAdd(&g_g1[cB + 0], accB.x);
        atomicAdd(&g_g1[cB + 1], accB.y);
        atomicAdd(&g_g1[cB + 2], accB.z);
        atomicAdd(&g_g1[cB + 3], accB.w);
    } else {
        // ---------------- W1 half: [4096 x 8192] ----------------
        const int rowBase = (blockIdx.x - 128) * 32;
        const float4* xv = (const float4*)g_x2;          // 2048 float4
        float4 xC[4];
        #pragma unroll
        for (int k = 0; k < 4; k++) xC[k] = xv[tid + k * 512];
        float4 acc[4] = {make_float4(0,0,0,0), make_float4(0,0,0,0),
                         make_float4(0,0,0,0), make_float4(0,0,0,0)};

        #pragma unroll 1
        for (int t = 0; t < 8; t++) {
            const int rb = rowBase + t * 4;
            const float4* base = (const float4*)W1 + (size_t)rb * 2048 + tid;

            float4 w[4][4];
            #pragma unroll
            for (int r = 0; r < 4; r++)
                #pragma unroll
                for (int k = 0; k < 4; k++)
                    w[r][k] = base[(size_t)r * 2048 + k * 512];

            #pragma unroll
            for (int r = 0; r < 4; r++) {
                float p = dot4(w[r][0], xC[0]) + dot4(w[r][1], xC[1])
                        + dot4(w[r][2], xC[2]) + dot4(w[r][3], xC[3]);
                #pragma unroll
                for (int o = 16; o; o >>= 1) p += __shfl_xor_sync(0xFFFFFFFFu, p, o);
                if (lane == 0) sp[r][warp] = p;
            }
            __syncthreads();
            if (tid < 4) {
                float s = 0.f;
                #pragma unroll
                for (int wi = 0; wi < 16; wi++) s += sp[tid][wi];
                float e = g_x1[rb + tid] - tanhf(s);
                se[tid] = e;
                g_e1[rb + tid] = e;
            }
            __syncthreads();
            #pragma unroll
            for (int r = 0; r < 4; r++) {
                const float e = se[r];
                #pragma unroll
                for (int k = 0; k < 4; k++) {
                    acc[k].x += e * w[r][k].x;  acc[k].y += e * w[r][k].y;
                    acc[k].z += e * w[r][k].z;  acc[k].w += e * w[r][k].w;
                }
            }
        }
        #pragma unroll
        for (int k = 0; k < 4; k++) {
            const int c = 4 * (tid + k * 512);
            atomicAdd(&g_g2[c + 0], acc[k].x);
            atomicAdd(&g_g2[c + 1], acc[k].y);
            atomicAdd(&g_g2[c + 2], acc[k].z);
            atomicAdd(&g_g2[c + 3], acc[k].w);
        }
    }
}

// ---------------------------------------------------------------------------
// State update; zeroes grads for next step.
// ---------------------------------------------------------------------------
__global__ void k_update() {
    int i = blockIdx.x * blockDim.x + threadIdx.x;
    if (i < N1) {
        float gr = fminf(fmaxf(-g_e1[i] + g_g1[i], -1.f), 1.f);
        g_x1[i] = tanhf(g_x1[i] + 0.01f * gr);
        g_g1[i] = 0.f;
    } else {
        int c = i - N1;
        float x2 = g_x2[c];
        float gr = fminf(fmaxf(-x2 + g_g2[c], -1.f), 1.f);
        g_x2[c] = tanhf(x2 + 0.01f * gr);
        g_g2[c] = 0.f;
    }
}

// ---------------------------------------------------------------------------
// Final step: err = ||x0 - tanh(W0@x1)||^2 + ||x1 - tanh(W1@x2)||^2 + ||x2||^2
// ---------------------------------------------------------------------------
__global__ void k_final(const float* __restrict__ x0,
                        const float* __restrict__ W0,
                        const float* __restrict__ W1,
                        float* __restrict__ out) {
    __shared__ float s_part[8];
    int warpInBlock = threadIdx.x >> 5;
    int warp = (blockIdx.x * blockDim.x + threadIdx.x) >> 5;
    int lane = threadIdx.x & 31;

    float local = 0.f;
    if (warp < N0) {
        const float4* row = (const float4*)(W0 + (size_t)warp * N1);
        const float4* xv  = (const float4*)g_x1;
        float acc = 0.f;
        #pragma unroll 4
        for (int i = lane; i < N1 / 4; i += 32) acc += dot4(row[i], xv[i]);
        #pragma unroll
        for (int o = 16; o; o >>= 1) acc += __shfl_xor_sync(0xFFFFFFFFu, acc, o);
        if (lane == 0) {
            float e = x0[warp] - tanhf(acc);
            float x2v = g_x2[warp];
            local = e * e + x2v * x2v;
        }
    } else {
        int r = warp - N0;
        const float4* row = (const float4*)(W1 + (size_t)r * N2);
        const float4* xv  = (const float4*)g_x2;
        float acc = 0.f;
        #pragma unroll 4
        for (int i = lane; i < N2 / 4; i += 32) acc += dot4(row[i], xv[i]);
        #pragma unroll
        for (int o = 16; o; o >>= 1) acc += __shfl_xor_sync(0xFFFFFFFFu, acc, o);
        if (lane == 0) {
            float e = g_x1[r] - tanhf(acc);
            local = e * e;
        }
    }

    if (lane == 0) s_part[warpInBlock] = local;
    __syncthreads();
    if (threadIdx.x == 0) {
        float s = 0.f;
        #pragma unroll
        for (int w = 0; w < 8; w++) s += s_part[w];
        atomicAdd(out, s);
    }
}

// ---------------------------------------------------------------------------
extern "C" void kernel_launch(void* const* d_in, const int* in_sizes, int n_in,
                              void* d_out, int out_size) {
    const float* x0 = (const float*)d_in[0];
    const float* W0 = (const float*)d_in[1];
    const float* W1 = (const float*)d_in[2];
    float* out = (float*)d_out;

    const int STEPS = 10;

    k_init<<<32, 256>>>(out);
    for (int s = 0; s < STEPS - 1; s++) {
        k_step<<<256, 512>>>(x0, W0, W1);
        k_update<<<(N1 + N2) / 256, 256>>>();
    }
    k_final<<<(N0 + N1) / 8, 256>>>(x0, W0, W1, out);
}